// round 15
// baseline (speedup 1.0000x reference)
#include <cuda_runtime.h>

#define NHID 20
#define NJH  (NHID / 2)     // half of the outputs per pass
#define TPB  128
#define PPT  2

typedef unsigned long long u64;

struct CParams {
    u64 Wc[6 * NHID * NJH];   // [l][k][j0..9] transposed splat pairs (const share)
    u64 Blo[6 * NJH];         // biases j0..9
    u64 Bhi[6 * NJH];         // biases j10..19
    u64 W0[NHID];
    u64 B0[NHID];
    u64 W7[NHID];
    u64 B7;
};

__constant__ CParams cP;
__device__   CParams gStage;
__device__   u64     gWs[6 * NHID * NJH];   // [l][k][j10..19] (smem share)

static __device__ __forceinline__ u64 pack2f(float lo, float hi) {
    u64 r;
    unsigned a = __float_as_uint(lo), b = __float_as_uint(hi);
    asm("mov.b64 %0, {%1, %2};" : "=l"(r) : "r"(a), "r"(b));
    return r;
}
static __device__ __forceinline__ void unpack2f(u64 v, float& lo, float& hi) {
    unsigned a, b;
    asm("mov.b64 {%0, %1}, %2;" : "=r"(a), "=r"(b) : "l"(v));
    lo = __uint_as_float(a);
    hi = __uint_as_float(b);
}
static __device__ __forceinline__ u64 fma2(u64 a, u64 b, u64 c) {
    u64 d;
    asm("fma.rn.f32x2 %0, %1, %2, %3;" : "=l"(d) : "l"(a), "l"(b), "l"(c));
    return d;
}
static __device__ __forceinline__ u64 mul2(u64 a, u64 b) {
    u64 d;
    asm("mul.rn.f32x2 %0, %1, %2;" : "=l"(d) : "l"(a), "l"(b));
    return d;
}
static __device__ __forceinline__ u64 add2(u64 a, u64 b) {
    u64 d;
    asm("add.rn.f32x2 %0, %1, %2;" : "=l"(d) : "l"(a), "l"(b));
    return d;
}
static __device__ __forceinline__ float ex2f(float x) {
    float r;
    asm("ex2.approx.f32 %0, %1;" : "=f"(r) : "f"(x));
    return r;
}
static __device__ __forceinline__ float rcpf(float x) {
    float r;
    asm("rcp.approx.f32 %0, %1;" : "=f"(r) : "f"(x));
    return r;
}

// silu pair: x * 1/(1+e^-x). 3 f32x2 fma-pipe ops + 4 MUFU.
static __device__ __forceinline__ u64 silu2(u64 x2, u64 negl2e2, u64 one2) {
    u64 m = mul2(x2, negl2e2);
    float mlo, mhi; unpack2f(m, mlo, mhi);
    u64 e = pack2f(ex2f(mlo), ex2f(mhi));
    u64 d = add2(e, one2);
    float dlo, dhi; unpack2f(d, dlo, dhi);
    u64 r = pack2f(rcpf(dlo), rcpf(dhi));
    return mul2(x2, r);
}

// Prep: split transposed splat tables by j-half.
__global__ void prep_kernel(
    const float* __restrict__ W0, const float* __restrict__ b0,
    const float* __restrict__ W1, const float* __restrict__ b1,
    const float* __restrict__ W2, const float* __restrict__ b2,
    const float* __restrict__ W3, const float* __restrict__ b3,
    const float* __restrict__ W4, const float* __restrict__ b4,
    const float* __restrict__ W5, const float* __restrict__ b5,
    const float* __restrict__ W6, const float* __restrict__ b6,
    const float* __restrict__ W7, const float* __restrict__ b7)
{
    const int tid = blockIdx.x * blockDim.x + threadIdx.x;
    const int nthr = gridDim.x * blockDim.x;

    for (int i = tid; i < 6 * NHID * NHID; i += nthr) {
        int l = i / (NHID * NHID);
        int r = i - l * (NHID * NHID);
        int k = r / NHID;          // input index
        int j = r - k * NHID;      // output index
        int src = j * NHID + k;    // row-major W[j][k]
        float w;
        switch (l) {
            case 0: w = W1[src]; break;
            case 1: w = W2[src]; break;
            case 2: w = W3[src]; break;
            case 3: w = W4[src]; break;
            case 4: w = W5[src]; break;
            default: w = W6[src]; break;
        }
        u64 p = pack2f(w, w);
        if (j < NJH)
            gStage.Wc[(l * NHID + k) * NJH + j] = p;
        else
            gWs[(l * NHID + k) * NJH + (j - NJH)] = p;
    }
    for (int i = tid; i < 6 * NHID; i += nthr) {
        int l = i / NHID;
        int r = i - l * NHID;
        float w;
        switch (l) {
            case 0: w = b1[r]; break;
            case 1: w = b2[r]; break;
            case 2: w = b3[r]; break;
            case 3: w = b4[r]; break;
            case 4: w = b5[r]; break;
            default: w = b6[r]; break;
        }
        u64 p = pack2f(w, w);
        if (r < NJH) gStage.Blo[l * NJH + r] = p;
        else         gStage.Bhi[l * NJH + (r - NJH)] = p;
    }
    for (int i = tid; i < NHID; i += nthr) {
        gStage.W0[i] = pack2f(W0[i], W0[i]);
        gStage.B0[i] = pack2f(b0[i], b0[i]);
        gStage.W7[i] = pack2f(W7[i], W7[i]);
    }
    if (tid == 0) gStage.B7 = pack2f(b7[0], b7[0]);
}

__global__ void __launch_bounds__(TPB, 5)   // 102-reg budget, arch need ~85
SpringEquationNN_kernel(const float* __restrict__ t,
                        float* __restrict__ out, int n)
{
    // smem: j10..19 weight share + thread-private parking for pass-A results
    __shared__ __align__(16) u64 sWs[6 * NHID * NJH];
    __shared__ __align__(16) u64 sPriv[(NJH / 2) * TPB * 2];

    const int tid = threadIdx.x;
    for (int i = tid; i < 6 * NHID * NJH; i += TPB)
        sWs[i] = gWs[i];
    __syncthreads();

    const u64 NEGL2E2 = pack2f(-1.442695041f, -1.442695041f);
    const u64 ONE2    = pack2f(1.0f, 1.0f);

    const int base = (blockIdx.x * TPB + tid) * PPT;
    if (base >= n) return;

    float tx, ty;
    if (base + 2 <= n) {
        float2 v = *reinterpret_cast<const float2*>(t + base);
        tx = v.x; ty = v.y;
    } else {
        tx = t[base]; ty = 0.0f;
    }
    const u64 x0 = pack2f(tx, ty);

    u64 h[NHID];

    // Layer 0: 1 -> 20 (constant, immediate offsets)
    #pragma unroll
    for (int j = 0; j < NHID; j++)
        h[j] = silu2(fma2(x0, cP.W0[j], cP.B0[j]), NEGL2E2, ONE2);

    // Hidden layers: two passes of 10 outputs each to keep live regs ~80.
    for (int l = 0; l < 6; l++) {
        const ulonglong2* wc =
            reinterpret_cast<const ulonglong2*>(cP.Wc + l * NHID * NJH);
        const ulonglong2* ws =
            reinterpret_cast<const ulonglong2*>(sWs + l * NHID * NJH);
        const ulonglong2* blo =
            reinterpret_cast<const ulonglong2*>(cP.Blo + l * NJH);
        const ulonglong2* bhi =
            reinterpret_cast<const ulonglong2*>(cP.Bhi + l * NJH);

        // ---- Pass A: outputs j0..9, weights via constant port ----
        {
            u64 acc[NJH];
            #pragma unroll
            for (int j2 = 0; j2 < NJH / 2; j2++) {
                ulonglong2 bb = blo[j2];
                acc[2 * j2]     = bb.x;
                acc[2 * j2 + 1] = bb.y;
            }
            #pragma unroll
            for (int k = 0; k < NHID; k++) {
                const u64 hk = h[k];
                #pragma unroll
                for (int j2 = 0; j2 < NJH / 2; j2++) {
                    ulonglong2 w = wc[k * (NJH / 2) + j2];   // LDC.128
                    acc[2 * j2]     = fma2(hk, w.x, acc[2 * j2]);
                    acc[2 * j2 + 1] = fma2(hk, w.y, acc[2 * j2 + 1]);
                }
            }
            // silu + park in thread-private smem (pass B still needs h intact)
            #pragma unroll
            for (int j2 = 0; j2 < NJH / 2; j2++) {
                ulonglong2 v;
                v.x = silu2(acc[2 * j2],     NEGL2E2, ONE2);
                v.y = silu2(acc[2 * j2 + 1], NEGL2E2, ONE2);
                *reinterpret_cast<ulonglong2*>(
                    &sPriv[(j2 * TPB + tid) * 2]) = v;       // STS.128
            }
        }

        // ---- Pass B: outputs j10..19, weights via shared crossbar ----
        {
            u64 acc[NJH];
            #pragma unroll
            for (int j2 = 0; j2 < NJH / 2; j2++) {
                ulonglong2 bb = bhi[j2];
                acc[2 * j2]     = bb.x;
                acc[2 * j2 + 1] = bb.y;
            }
            #pragma unroll
            for (int k = 0; k < NHID; k++) {
                const u64 hk = h[k];
                #pragma unroll
                for (int j2 = 0; j2 < NJH / 2; j2++) {
                    ulonglong2 w = ws[k * (NJH / 2) + j2];   // LDS.128 bcast
                    acc[2 * j2]     = fma2(hk, w.x, acc[2 * j2]);
                    acc[2 * j2 + 1] = fma2(hk, w.y, acc[2 * j2 + 1]);
                }
            }
            #pragma unroll
            for (int j = 0; j < NJH; j++)
                h[NJH + j] = silu2(acc[j], NEGL2E2, ONE2);
        }

        // Reload pass-A results into h[0..9]
        #pragma unroll
        for (int j2 = 0; j2 < NJH / 2; j2++) {
            ulonglong2 v = *reinterpret_cast<const ulonglong2*>(
                &sPriv[(j2 * TPB + tid) * 2]);               // LDS.128
            h[2 * j2]     = v.x;
            h[2 * j2 + 1] = v.y;
        }
    }

    // Output layer: 20 -> 1 (constant, dual chains)
    {
        const ulonglong2* w7 = reinterpret_cast<const ulonglong2*>(cP.W7);
        u64 accE = cP.B7;
        u64 accO = 0ull;
        #pragma unroll
        for (int k2 = 0; k2 < NHID / 2; k2++) {
            ulonglong2 w = w7[k2];
            accE = fma2(h[2 * k2],     w.x, accE);
            accO = fma2(h[2 * k2 + 1], w.y, accO);
        }
        u64 a = add2(accE, accO);
        float o0, o1;
        unpack2f(a, o0, o1);
        if (base + 2 <= n) {
            *reinterpret_cast<float2*>(out + base) = make_float2(o0, o1);
        } else {
            out[base] = o0;
        }
    }
}

extern "C" void kernel_launch(void* const* d_in, const int* in_sizes, int n_in,
                              void* d_out, int out_size)
{
    const float* t  = (const float*)d_in[0];
    const float* W0 = (const float*)d_in[1];
    const float* b0 = (const float*)d_in[2];
    const float* W1 = (const float*)d_in[3];
    const float* b1 = (const float*)d_in[4];
    const float* W2 = (const float*)d_in[5];
    const float* b2 = (const float*)d_in[6];
    const float* W3 = (const float*)d_in[7];
    const float* b3 = (const float*)d_in[8];
    const float* W4 = (const float*)d_in[9];
    const float* b4 = (const float*)d_in[10];
    const float* W5 = (const float*)d_in[11];
    const float* b5 = (const float*)d_in[12];
    const float* W6 = (const float*)d_in[13];
    const float* b6 = (const float*)d_in[14];
    const float* W7 = (const float*)d_in[15];
    const float* b7 = (const float*)d_in[16];

    const int n = in_sizes[0];
    float* out = (float*)d_out;

    // 1) Build j-half-split splat tables.
    prep_kernel<<<4, 256>>>(W0, b0, W1, b1, W2, b2, W3, b3,
                            W4, b4, W5, b5, W6, b6, W7, b7);

    // 2) Stage -> constant aperture (graph-capturable D2D memcpy).
    void* cAddr = nullptr;
    void* gAddr = nullptr;
    cudaGetSymbolAddress(&cAddr, cP);
    cudaGetSymbolAddress(&gAddr, gStage);
    cudaMemcpyAsync(cAddr, gAddr, sizeof(CParams), cudaMemcpyDeviceToDevice);

    // 3) Main evaluation.
    const int pts_per_block = TPB * PPT;
    const int grid = (n + pts_per_block - 1) / pts_per_block;
    SpringEquationNN_kernel<<<grid, TPB>>>(t, out, n);
}

// round 16
// speedup vs baseline: 8.3192x; 8.3192x over previous
#include <cuda_runtime.h>

#define NHID 20
#define TPB  256
#define PPT  2
#define NWH  (6 * NHID * NHID)

typedef unsigned long long u64;

struct CParams {
    u64 Wt[NWH];        // hidden weights, transposed splats: [l][k*NHID + j]
    u64 B[6 * NHID];    // hidden biases, splats
    u64 W0[NHID];
    u64 B0[NHID];
    u64 W7[NHID];
    u64 B7;
};

__constant__ CParams cP;
__device__   CParams gStage;

static __device__ __forceinline__ u64 pack2f(float lo, float hi) {
    u64 r;
    unsigned a = __float_as_uint(lo), b = __float_as_uint(hi);
    asm("mov.b64 %0, {%1, %2};" : "=l"(r) : "r"(a), "r"(b));
    return r;
}
static __device__ __forceinline__ void unpack2f(u64 v, float& lo, float& hi) {
    unsigned a, b;
    asm("mov.b64 {%0, %1}, %2;" : "=r"(a), "=r"(b) : "l"(v));
    lo = __uint_as_float(a);
    hi = __uint_as_float(b);
}
static __device__ __forceinline__ u64 fma2(u64 a, u64 b, u64 c) {
    u64 d;
    asm("fma.rn.f32x2 %0, %1, %2, %3;" : "=l"(d) : "l"(a), "l"(b), "l"(c));
    return d;
}
static __device__ __forceinline__ u64 mul2(u64 a, u64 b) {
    u64 d;
    asm("mul.rn.f32x2 %0, %1, %2;" : "=l"(d) : "l"(a), "l"(b));
    return d;
}
static __device__ __forceinline__ float tanhf_approx(float x) {
    float r;
    asm("tanh.approx.f32 %0, %1;" : "=f"(r) : "f"(x));
    return r;
}

// silu pair via tanh: x * 0.5 * (1 + tanh(x/2)).
// 3 f32x2 fma-pipe ops + 2 MUFU (vs 4 MUFU for the exp form).
static __device__ __forceinline__ u64 silu2(u64 x2, u64 half2) {
    u64 m = mul2(x2, half2);                 // x/2
    float mlo, mhi; unpack2f(m, mlo, mhi);
    u64 t = pack2f(tanhf_approx(mlo), tanhf_approx(mhi));
    u64 s = fma2(t, half2, half2);           // 0.5 + 0.5*tanh(x/2) = sigmoid
    return mul2(x2, s);
}

// Prep: build transposed splat-pair weight tables in gStage.
__global__ void prep_kernel(
    const float* __restrict__ W0, const float* __restrict__ b0,
    const float* __restrict__ W1, const float* __restrict__ b1,
    const float* __restrict__ W2, const float* __restrict__ b2,
    const float* __restrict__ W3, const float* __restrict__ b3,
    const float* __restrict__ W4, const float* __restrict__ b4,
    const float* __restrict__ W5, const float* __restrict__ b5,
    const float* __restrict__ W6, const float* __restrict__ b6,
    const float* __restrict__ W7, const float* __restrict__ b7)
{
    const int tid = blockIdx.x * blockDim.x + threadIdx.x;
    const int nthr = gridDim.x * blockDim.x;

    for (int i = tid; i < NWH; i += nthr) {
        int l = i / (NHID * NHID);
        int r = i - l * (NHID * NHID);
        int k = r / NHID;
        int j = r - k * NHID;
        int src = j * NHID + k;   // row-major W[j][k]
        float w;
        switch (l) {
            case 0: w = W1[src]; break;
            case 1: w = W2[src]; break;
            case 2: w = W3[src]; break;
            case 3: w = W4[src]; break;
            case 4: w = W5[src]; break;
            default: w = W6[src]; break;
        }
        gStage.Wt[i] = pack2f(w, w);
    }
    for (int i = tid; i < 6 * NHID; i += nthr) {
        int l = i / NHID;
        int r = i - l * NHID;
        float w;
        switch (l) {
            case 0: w = b1[r]; break;
            case 1: w = b2[r]; break;
            case 2: w = b3[r]; break;
            case 3: w = b4[r]; break;
            case 4: w = b5[r]; break;
            default: w = b6[r]; break;
        }
        gStage.B[i] = pack2f(w, w);
    }
    for (int i = tid; i < NHID; i += nthr) {
        gStage.W0[i] = pack2f(W0[i], W0[i]);
        gStage.B0[i] = pack2f(b0[i], b0[i]);
        gStage.W7[i] = pack2f(W7[i], W7[i]);
    }
    if (tid == 0) gStage.B7 = pack2f(b7[0], b7[0]);
}

__global__ void __launch_bounds__(TPB, 2)   // 128 regs -> 4 warps/SMSP (R10 cfg)
SpringEquationNN_kernel(const float* __restrict__ t,
                        float* __restrict__ out, int n)
{
    const u64 HALF2 = pack2f(0.5f, 0.5f);

    const int base = (blockIdx.x * TPB + threadIdx.x) * PPT;
    if (base >= n) return;

    float tx, ty;
    if (base + 2 <= n) {
        float2 v = *reinterpret_cast<const float2*>(t + base);
        tx = v.x; ty = v.y;
    } else {
        tx = t[base]; ty = 0.0f;
    }
    const u64 x0 = pack2f(tx, ty);

    u64 h[NHID];

    // Layer 0: 1 -> 20 (constant, immediate offsets)
    #pragma unroll
    for (int j = 0; j < NHID; j++)
        h[j] = silu2(fma2(x0, cP.W0[j], cP.B0[j]), HALF2);

    // Hidden layers 1..6, FULLY UNROLLED: lets ptxas overlap trailing silus
    // of layer l with the leading LDC+FMA stream of layer l+1, and folds all
    // weight offsets into LDC immediates.
    #pragma unroll
    for (int l = 0; l < 6; l++) {
        const ulonglong2* w2 =
            reinterpret_cast<const ulonglong2*>(cP.Wt + l * NHID * NHID);
        const ulonglong2* b2v =
            reinterpret_cast<const ulonglong2*>(cP.B + l * NHID);

        u64 acc[NHID];
        #pragma unroll
        for (int j2 = 0; j2 < NHID / 2; j2++) {
            ulonglong2 bb = b2v[j2];
            acc[2 * j2]     = bb.x;
            acc[2 * j2 + 1] = bb.y;
        }

        #pragma unroll
        for (int k = 0; k < NHID; k++) {
            const u64 hk = h[k];
            #pragma unroll
            for (int j2 = 0; j2 < NHID / 2; j2++) {
                ulonglong2 w = w2[k * (NHID / 2) + j2];  // LDC.128, imm offset
                acc[2 * j2]     = fma2(hk, w.x, acc[2 * j2]);
                acc[2 * j2 + 1] = fma2(hk, w.y, acc[2 * j2 + 1]);
            }
        }

        #pragma unroll
        for (int j = 0; j < NHID; j++)
            h[j] = silu2(acc[j], HALF2);
    }

    // Output layer: 20 -> 1 (constant, dual chains)
    {
        const ulonglong2* w7 = reinterpret_cast<const ulonglong2*>(cP.W7);
        u64 accE = cP.B7;
        u64 accO = 0ull;
        #pragma unroll
        for (int k2 = 0; k2 < NHID / 2; k2++) {
            ulonglong2 w = w7[k2];
            accE = fma2(h[2 * k2],     w.x, accE);
            accO = fma2(h[2 * k2 + 1], w.y, accO);
        }
        // merge chains
        float e0, e1, o0f, o1f;
        unpack2f(accE, e0, e1);
        unpack2f(accO, o0f, o1f);
        float r0 = e0 + o0f;
        float r1 = e1 + o1f;
        if (base + 2 <= n) {
            *reinterpret_cast<float2*>(out + base) = make_float2(r0, r1);
        } else {
            out[base] = r0;
        }
    }
}

extern "C" void kernel_launch(void* const* d_in, const int* in_sizes, int n_in,
                              void* d_out, int out_size)
{
    const float* t  = (const float*)d_in[0];
    const float* W0 = (const float*)d_in[1];
    const float* b0 = (const float*)d_in[2];
    const float* W1 = (const float*)d_in[3];
    const float* b1 = (const float*)d_in[4];
    const float* W2 = (const float*)d_in[5];
    const float* b2 = (const float*)d_in[6];
    const float* W3 = (const float*)d_in[7];
    const float* b3 = (const float*)d_in[8];
    const float* W4 = (const float*)d_in[9];
    const float* b4 = (const float*)d_in[10];
    const float* W5 = (const float*)d_in[11];
    const float* b5 = (const float*)d_in[12];
    const float* W6 = (const float*)d_in[13];
    const float* b6 = (const float*)d_in[14];
    const float* W7 = (const float*)d_in[15];
    const float* b7 = (const float*)d_in[16];

    const int n = in_sizes[0];
    float* out = (float*)d_out;

    // 1) Build splat tables in device-global staging.
    prep_kernel<<<4, 256>>>(W0, b0, W1, b1, W2, b2, W3, b3,
                            W4, b4, W5, b5, W6, b6, W7, b7);

    // 2) Stage -> constant aperture (graph-capturable D2D memcpy).
    void* cAddr = nullptr;
    void* gAddr = nullptr;
    cudaGetSymbolAddress(&cAddr, cP);
    cudaGetSymbolAddress(&gAddr, gStage);
    cudaMemcpyAsync(cAddr, gAddr, sizeof(CParams), cudaMemcpyDeviceToDevice);

    // 3) Main evaluation.
    const int pts_per_block = TPB * PPT;
    const int grid = (n + pts_per_block - 1) / pts_per_block;
    SpringEquationNN_kernel<<<grid, TPB>>>(t, out, n);
}